// round 1
// baseline (speedup 1.0000x reference)
#include <cuda_runtime.h>
#include <math.h>

#define Bsz   64
#define Dd    1024
#define AEDp  64
#define DMp   1088
#define Hh    8
#define HDp   136
#define DFFp  2048
#define SEQ   512
#define Rr    487
#define MROWS (Bsz*SEQ)     /* 32768 */
#define GHEADS (Bsz*Hh)     /* 512  */

// ---------------- scratch (device globals; no runtime allocation) ----------
__device__ float g_S  [(size_t)MROWS*DMp];          // 142.6 MB  running activations
__device__ float g_QKV[(size_t)MROWS*3*DMp];        // 428 MB    qkv / generic scratch
__device__ float g_Q  [(size_t)GHEADS*SEQ*HDp];     // per-head Q
__device__ float g_K  [(size_t)GHEADS*SEQ*HDp];     // per-head K
__device__ float g_Vt [(size_t)GHEADS*HDp*SEQ];     // per-head V transposed
__device__ float g_P  [(size_t)GHEADS*SEQ*SEQ];     // 537 MB    attention probs
__device__ float g_ATT[(size_t)MROWS*DMp];          // attention output
__device__ float g_FFN[(size_t)MROWS*DFFp];         // ffn hidden
__device__ float g_bias[Bsz*SEQ];                   // key-padding bias (-1e9 / 0)

// ---------------- build S tensor + mask bias --------------------------------
__global__ void build_S(const float* __restrict__ q, const float* __restrict__ sa,
                        const float* __restrict__ si, const float* __restrict__ ref,
                        const int* __restrict__ na, const int* __restrict__ ni)
{
    size_t idx = (size_t)blockIdx.x * blockDim.x + threadIdx.x;
    if (idx >= (size_t)MROWS * DMp) return;
    int c = (int)(idx % DMp);
    size_t row = idx / DMp;
    int t = (int)(row % SEQ);
    int b = (int)(row / SEQ);
    float v;
    if (t == 0)       v = (c < Dd) ? q  [(size_t)b*Dd + c]                     : 0.f;
    else if (t < 13)  v = (c < Dd) ? sa [((size_t)b*12 + (t-1))*Dd + c]        : 1.f;
    else if (t < 25)  v = (c < Dd) ? si [((size_t)b*12 + (t-13))*Dd + c]       : -1.f;
    else              v = (c < Dd) ? ref[((size_t)b*Rr + (t-25))*Dd + c]       : 0.f;
    g_S[idx] = v;
    if (c == 0) {
        int ra = na[b], ri = ni[b];
        bool m = (t == 0)
              || (t >= 1  && t < 13 && t < ra + 1)
              || (t >= 13 && t < 25 && t < ri + 13);
        g_bias[b*SEQ + t] = m ? -1.0e9f : 0.f;
    }
}

// ---------------- shared GEMM mainloop (C = A @ B^T), 128x128x8 -------------
__device__ __forceinline__ void mm_tile(
    const float* __restrict__ A, const float* __restrict__ Bw, int K,
    int aRow, int bRow, int M, int N,
    float (&acc)[8][8], float (*As)[128], float (*Bs)[128],
    int lr, int lc, int tx, int ty)
{
    bool aval = aRow < M;
    bool bval = bRow < N;
    const float* Ap = A  + (size_t)aRow * K;
    const float* Bp = Bw + (size_t)bRow * K;
    for (int k0 = 0; k0 < K; k0 += 8) {
        float4 av = aval ? *(const float4*)(Ap + k0 + lc) : make_float4(0.f,0.f,0.f,0.f);
        float4 bv = bval ? *(const float4*)(Bp + k0 + lc) : make_float4(0.f,0.f,0.f,0.f);
        As[lc+0][lr]=av.x; As[lc+1][lr]=av.y; As[lc+2][lr]=av.z; As[lc+3][lr]=av.w;
        Bs[lc+0][lr]=bv.x; Bs[lc+1][lr]=bv.y; Bs[lc+2][lr]=bv.z; Bs[lc+3][lr]=bv.w;
        __syncthreads();
        #pragma unroll
        for (int kk = 0; kk < 8; kk++) {
            float a[8], b[8];
            *(float4*)(a)   = *(const float4*)(&As[kk][ty*8]);
            *(float4*)(a+4) = *(const float4*)(&As[kk][ty*8+4]);
            *(float4*)(b)   = *(const float4*)(&Bs[kk][tx*8]);
            *(float4*)(b+4) = *(const float4*)(&Bs[kk][tx*8+4]);
            #pragma unroll
            for (int i = 0; i < 8; i++)
                #pragma unroll
                for (int j = 0; j < 8; j++)
                    acc[i][j] = fmaf(a[i], b[j], acc[i][j]);
        }
        __syncthreads();
    }
}

// ---------------- generic GEMM: C = A @ W^T + bias, optional relu ----------
__global__ void __launch_bounds__(256, 2)
gemm_nt(const float* __restrict__ A, const float* __restrict__ Bw,
        const float* __restrict__ bias, float* __restrict__ C,
        int M, int N, int K, int relu)
{
    __shared__ float As[8][128];
    __shared__ float Bs[8][128];
    int tid = threadIdx.x;
    int lr = tid >> 1, lc = (tid & 1) * 4, tx = tid & 15, ty = tid >> 4;
    int bm = blockIdx.y * 128, bn = blockIdx.x * 128;
    float acc[8][8] = {};
    mm_tile(A, Bw, K, bm + lr, bn + lr, M, N, acc, As, Bs, lr, lc, tx, ty);
    #pragma unroll
    for (int i = 0; i < 8; i++) {
        int row = bm + ty*8 + i;
        if (row >= M) continue;
        float* crow = C + (size_t)row * N;
        #pragma unroll
        for (int j = 0; j < 8; j++) {
            int col = bn + tx*8 + j;
            if (col >= N) continue;
            float v = acc[i][j] + bias[col];
            if (relu) v = fmaxf(v, 0.f);
            crow[col] = v;
        }
    }
}

// ---------------- unpack QKV into per-head buffers ---------------------------
__global__ void unpack_qkv()
{
    size_t idx = (size_t)blockIdx.x * blockDim.x + threadIdx.x;
    if (idx >= (size_t)MROWS * DMp) return;
    int c = (int)(idx % DMp);
    size_t row = idx / DMp;
    int t = (int)(row % SEQ);
    int b = (int)(row / SEQ);
    int h = c / HDp, d = c % HDp;
    const float* src = g_QKV + row * (size_t)(3*DMp);
    size_t gh = (size_t)(b*Hh + h);
    g_Q [(gh*SEQ + t)*HDp + d] = src[c];
    g_K [(gh*SEQ + t)*HDp + d] = src[DMp + c];
    g_Vt[(gh*HDp + d)*SEQ + t] = src[2*DMp + c];
}

// ---------------- batched scores: P = scale*Q@K^T + maskbias ----------------
__global__ void __launch_bounds__(256, 2) gemm_scores()
{
    __shared__ float As[8][128];
    __shared__ float Bs[8][128];
    int g = blockIdx.z, b = g >> 3;
    const float* A  = g_Q + (size_t)g * SEQ * HDp;
    const float* Bw = g_K + (size_t)g * SEQ * HDp;
    float* C = g_P + (size_t)g * SEQ * SEQ;
    int tid = threadIdx.x;
    int lr = tid >> 1, lc = (tid & 1) * 4, tx = tid & 15, ty = tid >> 4;
    int bm = blockIdx.y * 128, bn = blockIdx.x * 128;
    float acc[8][8] = {};
    mm_tile(A, Bw, HDp, bm + lr, bn + lr, SEQ, SEQ, acc, As, Bs, lr, lc, tx, ty);
    const float scale = rsqrtf((float)HDp);
    #pragma unroll
    for (int i = 0; i < 8; i++) {
        int row = bm + ty*8 + i;
        float* crow = C + (size_t)row * SEQ;
        #pragma unroll
        for (int j = 0; j < 8; j++) {
            int col = bn + tx*8 + j;
            crow[col] = acc[i][j] * scale + g_bias[b*SEQ + col];
        }
    }
}

// ---------------- row softmax over P ----------------------------------------
__global__ void softmax_rows()
{
    size_t row = blockIdx.x;
    float* p = g_P + row * SEQ;
    int tid = threadIdx.x;                 // 256 threads, 512 cols
    float v0 = p[tid], v1 = p[tid + 256];
    __shared__ float red[256];
    red[tid] = fmaxf(v0, v1);
    __syncthreads();
    for (int s = 128; s > 0; s >>= 1) {
        if (tid < s) red[tid] = fmaxf(red[tid], red[tid + s]);
        __syncthreads();
    }
    float m = red[0];
    __syncthreads();
    float e0 = expf(v0 - m), e1 = expf(v1 - m);
    red[tid] = e0 + e1;
    __syncthreads();
    for (int s = 128; s > 0; s >>= 1) {
        if (tid < s) red[tid] += red[tid + s];
        __syncthreads();
    }
    float inv = 1.f / red[0];
    p[tid]       = e0 * inv;
    p[tid + 256] = e1 * inv;
}

// ---------------- batched O = P @ V, scatter into head slot ------------------
__global__ void __launch_bounds__(256, 2) gemm_av()
{
    __shared__ float As[8][128];
    __shared__ float Bs[8][128];
    int g = blockIdx.z, b = g >> 3, h = g & 7;
    const float* A  = g_P  + (size_t)g * SEQ * SEQ;
    const float* Bw = g_Vt + (size_t)g * HDp * SEQ;
    int tid = threadIdx.x;
    int lr = tid >> 1, lc = (tid & 1) * 4, tx = tid & 15, ty = tid >> 4;
    int bm = blockIdx.y * 128, bn = blockIdx.x * 128;
    float acc[8][8] = {};
    mm_tile(A, Bw, SEQ, bm + lr, bn + lr, SEQ, HDp, acc, As, Bs, lr, lc, tx, ty);
    #pragma unroll
    for (int i = 0; i < 8; i++) {
        int row = bm + ty*8 + i;
        float* crow = g_ATT + ((size_t)b*SEQ + row) * DMp + h*HDp;
        #pragma unroll
        for (int j = 0; j < 8; j++) {
            int col = bn + tx*8 + j;
            if (col < HDp) crow[col] = acc[i][j];
        }
    }
}

// ---------------- residual add + layernorm (in place on x) -------------------
__global__ void add_ln(float* __restrict__ x, const float* __restrict__ o,
                       const float* __restrict__ w, const float* __restrict__ bb)
{
    size_t row = blockIdx.x;
    float* xr = x + row * DMp;
    const float* orow = o + row * DMp;
    int tid = threadIdx.x;                 // 256 threads, 1088 cols
    float vals[5];
    int cnt = 0;
    float s = 0.f;
    for (int i = tid; i < DMp; i += 256) { float v = xr[i] + orow[i]; vals[cnt++] = v; s += v; }
    __shared__ float red[256];
    red[tid] = s; __syncthreads();
    for (int st = 128; st > 0; st >>= 1) { if (tid < st) red[tid] += red[tid + st]; __syncthreads(); }
    float mu = red[0] * (1.f / DMp);
    __syncthreads();
    float s2 = 0.f;
    for (int k = 0; k < cnt; k++) { float d = vals[k] - mu; s2 += d * d; }
    red[tid] = s2; __syncthreads();
    for (int st = 128; st > 0; st >>= 1) { if (tid < st) red[tid] += red[tid + st]; __syncthreads(); }
    float rstd = rsqrtf(red[0] * (1.f / DMp) + 1e-5f);
    int k = 0;
    for (int i = tid; i < DMp; i += 256, k++)
        xr[i] = (vals[k] - mu) * rstd * w[i] + bb[i];
}

// ---------------- gather outputs ---------------------------------------------
__global__ void gather_out(float* __restrict__ out)
{
    size_t idx = (size_t)blockIdx.x * blockDim.x + threadIdx.x;
    if (idx >= (size_t)Bsz * 25 * 1024) return;
    int c = (int)(idx % 1024);
    int rem = (int)(idx / 1024);
    int t = rem % 25;
    int b = rem / 25;
    float v = g_S[((size_t)b*SEQ + t) * DMp + c];
    size_t o;
    if (t == 0)      o = (size_t)b * 1024 + c;                                  // q_out
    else if (t < 13) o = (size_t)Bsz*1024 + ((size_t)b*12 + (t-1))*1024 + c;    // sa_out
    else             o = (size_t)Bsz*1024 + (size_t)Bsz*12*1024
                       + ((size_t)b*12 + (t-13))*1024 + c;                      // si_out
    out[o] = v;
}

// ---------------- launch -----------------------------------------------------
extern "C" void kernel_launch(void* const* d_in, const int* in_sizes, int n_in,
                              void* d_out, int out_size)
{
    (void)in_sizes; (void)n_in; (void)out_size;
    const float* q    = (const float*)d_in[0];
    const float* sa   = (const float*)d_in[1];
    const float* si   = (const float*)d_in[2];
    const int*   na   = (const int*)  d_in[3];
    const int*   ni   = (const int*)  d_in[4];
    const float* ref  = (const float*)d_in[5];
    const float* Wqkv = (const float*)d_in[6];
    const float* bqkv = (const float*)d_in[7];
    const float* Wo   = (const float*)d_in[8];
    const float* bo   = (const float*)d_in[9];
    const float* ln1w = (const float*)d_in[10];
    const float* ln1b = (const float*)d_in[11];
    const float* W1   = (const float*)d_in[12];
    const float* b1   = (const float*)d_in[13];
    const float* W2   = (const float*)d_in[14];
    const float* b2   = (const float*)d_in[15];
    const float* ln2w = (const float*)d_in[16];
    const float* ln2b = (const float*)d_in[17];

    float *S, *QKV, *ATT, *FFN;
    cudaGetSymbolAddress((void**)&S,   g_S);
    cudaGetSymbolAddress((void**)&QKV, g_QKV);
    cudaGetSymbolAddress((void**)&ATT, g_ATT);
    cudaGetSymbolAddress((void**)&FFN, g_FFN);

    const int elems = MROWS * DMp;           // 35,651,584
    build_S<<<elems/256, 256>>>(q, sa, si, ref, na, ni);

    for (int l = 0; l < 2; l++) {
        const float* wqkv = Wqkv + (size_t)l * 3 * DMp * DMp;
        const float* bq   = bqkv + (size_t)l * 3 * DMp;
        // QKV projection: (32768 x 3264) = S (32768 x 1088) @ Wqkv^T
        gemm_nt<<<dim3((3*DMp + 127)/128, MROWS/128), 256>>>(S, wqkv, bq, QKV, MROWS, 3*DMp, DMp, 0);
        unpack_qkv<<<elems/256, 256>>>();
        // scores + mask bias (batched over 512 (b,h))
        gemm_scores<<<dim3(SEQ/128, SEQ/128, GHEADS), 256>>>();
        softmax_rows<<<GHEADS*SEQ, 256>>>();
        // attn @ V -> g_ATT
        gemm_av<<<dim3((HDp + 127)/128, SEQ/128, GHEADS), 256>>>();
        // output projection (scratch in QKV buffer)
        gemm_nt<<<dim3((DMp + 127)/128, MROWS/128), 256>>>(ATT, Wo + (size_t)l*DMp*DMp, bo + (size_t)l*DMp, QKV, MROWS, DMp, DMp, 0);
        add_ln<<<MROWS, 256>>>(S, QKV, ln1w + (size_t)l*DMp, ln1b + (size_t)l*DMp);
        // FFN
        gemm_nt<<<dim3(DFFp/128, MROWS/128), 256>>>(S, W1 + (size_t)l*DFFp*DMp, b1 + (size_t)l*DFFp, FFN, MROWS, DFFp, DMp, 1);
        gemm_nt<<<dim3((DMp + 127)/128, MROWS/128), 256>>>(FFN, W2 + (size_t)l*DMp*DFFp, b2 + (size_t)l*DMp, QKV, MROWS, DMp, DFFp, 0);
        add_ln<<<MROWS, 256>>>(S, QKV, ln2w + (size_t)l*DMp, ln2b + (size_t)l*DMp);
    }

    gather_out<<<(Bsz*25*1024)/256, 256>>>((float*)d_out);
}

// round 2
// speedup vs baseline: 1.6374x; 1.6374x over previous
#include <cuda_runtime.h>
#include <math.h>

#define Bsz   64
#define Dd    1024
#define AEDp  64
#define DMp   1088
#define Hh    8
#define HDp   136
#define DFFp  2048
#define SEQ   512
#define Rr    487
#define MROWS (Bsz*SEQ)     /* 32768 */
#define GHEADS (Bsz*Hh)     /* 512  */
#define M2    (Bsz*25)      /* 1600 compact rows for layer 2 */

// ---------------- scratch (device globals; no runtime allocation) ----------
__device__ float g_S  [(size_t)MROWS*DMp];          // running activations (full)
__device__ float g_QKV[(size_t)MROWS*3*DMp];        // qkv / generic scratch
__device__ float g_Q  [(size_t)GHEADS*SEQ*HDp];     // per-head Q (full or compact)
__device__ float g_K  [(size_t)GHEADS*SEQ*HDp];     // per-head K
__device__ float g_Vt [(size_t)GHEADS*HDp*SEQ];     // per-head V transposed
__device__ float g_P  [(size_t)GHEADS*SEQ*SEQ];     // attention probs
__device__ float g_ATT[(size_t)MROWS*DMp];          // attention output
__device__ float g_FFN[(size_t)MROWS*DFFp];         // ffn hidden / Qc scratch
__device__ float g_S2 [(size_t)M2*DMp];             // compact layer-2 activations
__device__ float g_O2 [(size_t)M2*DMp];             // compact layer-2 scratch
__device__ float g_bias[Bsz*SEQ];                   // key-padding bias

// ---------------- build S tensor + mask bias --------------------------------
__global__ void build_S(const float* __restrict__ q, const float* __restrict__ sa,
                        const float* __restrict__ si, const float* __restrict__ ref,
                        const int* __restrict__ na, const int* __restrict__ ni)
{
    size_t idx = (size_t)blockIdx.x * blockDim.x + threadIdx.x;
    if (idx >= (size_t)MROWS * DMp) return;
    int c = (int)(idx % DMp);
    size_t row = idx / DMp;
    int t = (int)(row % SEQ);
    int b = (int)(row / SEQ);
    float v;
    if (t == 0)       v = (c < Dd) ? q  [(size_t)b*Dd + c]              : 0.f;
    else if (t < 13)  v = (c < Dd) ? sa [((size_t)b*12 + (t-1))*Dd + c] : 1.f;
    else if (t < 25)  v = (c < Dd) ? si [((size_t)b*12 + (t-13))*Dd + c]: -1.f;
    else              v = (c < Dd) ? ref[((size_t)b*Rr + (t-25))*Dd + c]: 0.f;
    g_S[idx] = v;
    if (c == 0) {
        int ra = na[b], ri = ni[b];
        bool m = (t == 0)
              || (t >= 1  && t < 13 && t < ra + 1)
              || (t >= 13 && t < 25 && t < ri + 13);
        g_bias[b*SEQ + t] = m ? -1.0e9f : 0.f;
    }
}

// ---------------- double-buffered GEMM mainloop (C = A @ B^T) ---------------
__device__ __forceinline__ void compute_step(
    float (&acc)[8][8], const float (&As)[8][128], const float (&Bs)[8][128],
    int tx, int ty)
{
    #pragma unroll
    for (int kk = 0; kk < 8; kk++) {
        float a[8], b[8];
        *(float4*)(a)   = *(const float4*)(&As[kk][ty*8]);
        *(float4*)(a+4) = *(const float4*)(&As[kk][ty*8+4]);
        *(float4*)(b)   = *(const float4*)(&Bs[kk][tx*8]);
        *(float4*)(b+4) = *(const float4*)(&Bs[kk][tx*8+4]);
        #pragma unroll
        for (int i = 0; i < 8; i++)
            #pragma unroll
            for (int j = 0; j < 8; j++)
                acc[i][j] = fmaf(a[i], b[j], acc[i][j]);
    }
}

__device__ __forceinline__ void mm_tile_db(
    const float* __restrict__ A, const float* __restrict__ Bw, int K,
    int aRow, int bRow, int M, int N,
    float (&acc)[8][8], float (&As)[2][8][128], float (&Bs)[2][8][128],
    int lr, int lc, int tx, int ty)
{
    bool aval = aRow < M, bval = bRow < N;
    const float* Ap = A  + (size_t)aRow * K;
    const float* Bp = Bw + (size_t)bRow * K;
    const float4 z = make_float4(0.f,0.f,0.f,0.f);
    float4 av = aval ? *(const float4*)(Ap + lc) : z;
    float4 bv = bval ? *(const float4*)(Bp + lc) : z;
    As[0][lc+0][lr]=av.x; As[0][lc+1][lr]=av.y; As[0][lc+2][lr]=av.z; As[0][lc+3][lr]=av.w;
    Bs[0][lc+0][lr]=bv.x; Bs[0][lc+1][lr]=bv.y; Bs[0][lc+2][lr]=bv.z; Bs[0][lc+3][lr]=bv.w;
    __syncthreads();
    int buf = 0;
    for (int k0 = 8; k0 < K; k0 += 8) {
        float4 av2 = aval ? *(const float4*)(Ap + k0 + lc) : z;
        float4 bv2 = bval ? *(const float4*)(Bp + k0 + lc) : z;
        compute_step(acc, As[buf], Bs[buf], tx, ty);
        int nb = buf ^ 1;
        As[nb][lc+0][lr]=av2.x; As[nb][lc+1][lr]=av2.y; As[nb][lc+2][lr]=av2.z; As[nb][lc+3][lr]=av2.w;
        Bs[nb][lc+0][lr]=bv2.x; Bs[nb][lc+1][lr]=bv2.y; Bs[nb][lc+2][lr]=bv2.z; Bs[nb][lc+3][lr]=bv2.w;
        __syncthreads();
        buf = nb;
    }
    compute_step(acc, As[buf], Bs[buf], tx, ty);
}

// ---------------- generic GEMM: C = A @ W^T + bias, optional relu ----------
__global__ void __launch_bounds__(256, 2)
gemm_nt(const float* __restrict__ A, const float* __restrict__ Bw,
        const float* __restrict__ bias, float* __restrict__ C,
        int M, int N, int K, int relu)
{
    __shared__ float As[2][8][128];
    __shared__ float Bs[2][8][128];
    int tid = threadIdx.x;
    int lr = tid >> 1, lc = (tid & 1) * 4, tx = tid & 15, ty = tid >> 4;
    int bm = blockIdx.y * 128, bn = blockIdx.x * 128;
    float acc[8][8] = {};
    mm_tile_db(A, Bw, K, bm + lr, bn + lr, M, N, acc, As, Bs, lr, lc, tx, ty);
    #pragma unroll
    for (int i = 0; i < 8; i++) {
        int row = bm + ty*8 + i;
        if (row >= M) continue;
        float* crow = C + (size_t)row * N;
        #pragma unroll
        for (int j = 0; j < 8; j++) {
            int col = bn + tx*8 + j;
            if (col >= N) continue;
            float v = acc[i][j] + bias[col];
            if (relu) v = fmaxf(v, 0.f);
            crow[col] = v;
        }
    }
}

// ---------------- layer-1 unpack QKV into per-head buffers ------------------
__global__ void unpack_qkv()
{
    size_t idx = (size_t)blockIdx.x * blockDim.x + threadIdx.x;
    if (idx >= (size_t)MROWS * DMp) return;
    int c = (int)(idx % DMp);
    size_t row = idx / DMp;
    int t = (int)(row % SEQ);
    int b = (int)(row / SEQ);
    int h = c / HDp, d = c % HDp;
    const float* src = g_QKV + row * (size_t)(3*DMp);
    size_t gh = (size_t)(b*Hh + h);
    g_Q [(gh*SEQ + t)*HDp + d] = src[c];
    g_K [(gh*SEQ + t)*HDp + d] = src[DMp + c];
    g_Vt[(gh*HDp + d)*SEQ + t] = src[2*DMp + c];
}

// ---------------- layer-2 unpack KV (g_QKV holds rows of width 2176) --------
__global__ void unpack_kv()
{
    size_t idx = (size_t)blockIdx.x * blockDim.x + threadIdx.x;
    if (idx >= (size_t)MROWS * DMp) return;
    int c = (int)(idx % DMp);
    size_t row = idx / DMp;
    int t = (int)(row % SEQ);
    int b = (int)(row / SEQ);
    int h = c / HDp, d = c % HDp;
    const float* src = g_QKV + row * (size_t)(2*DMp);
    size_t gh = (size_t)(b*Hh + h);
    g_K [(gh*SEQ + t)*HDp + d] = src[c];
    g_Vt[(gh*HDp + d)*SEQ + t] = src[DMp + c];
}

// ---------------- gather compact layer-2 rows --------------------------------
__global__ void gather_S2()
{
    size_t idx = (size_t)blockIdx.x * blockDim.x + threadIdx.x;
    if (idx >= (size_t)M2 * DMp) return;
    int c = (int)(idx % DMp);
    int i = (int)(idx / DMp);
    int t = i % 25, b = i / 25;
    g_S2[idx] = g_S[((size_t)b*SEQ + t)*DMp + c];
}

// ---------------- layer-2 unpack compact Q (Qc lives in g_FFN) --------------
__global__ void unpack_q25()
{
    size_t idx = (size_t)blockIdx.x * blockDim.x + threadIdx.x;
    if (idx >= (size_t)M2 * DMp) return;
    int c = (int)(idx % DMp);
    int i = (int)(idx / DMp);
    int t = i % 25, b = i / 25;
    int h = c / HDp, d = c % HDp;
    int g = b*Hh + h;
    g_Q[((size_t)g*25 + t)*HDp + d] = g_FFN[(size_t)i*DMp + c];
}

// ---------------- layer-1 batched scores: P = scale*Q@K^T + maskbias --------
__global__ void __launch_bounds__(256, 2) gemm_scores()
{
    __shared__ float As[2][8][128];
    __shared__ float Bs[2][8][128];
    int g = blockIdx.z, b = g >> 3;
    const float* A  = g_Q + (size_t)g * SEQ * HDp;
    const float* Bw = g_K + (size_t)g * SEQ * HDp;
    float* C = g_P + (size_t)g * SEQ * SEQ;
    int tid = threadIdx.x;
    int lr = tid >> 1, lc = (tid & 1) * 4, tx = tid & 15, ty = tid >> 4;
    int bm = blockIdx.y * 128, bn = blockIdx.x * 128;
    float acc[8][8] = {};
    mm_tile_db(A, Bw, HDp, bm + lr, bn + lr, SEQ, SEQ, acc, As, Bs, lr, lc, tx, ty);
    const float scale = rsqrtf((float)HDp);
    #pragma unroll
    for (int i = 0; i < 8; i++) {
        int row = bm + ty*8 + i;
        float* crow = C + (size_t)row * SEQ;
        #pragma unroll
        for (int j = 0; j < 8; j++) {
            int col = bn + tx*8 + j;
            crow[col] = acc[i][j] * scale + g_bias[b*SEQ + col];
        }
    }
}

// ---------------- layer-2 compact scores: 25 x 512 per head -----------------
__global__ void __launch_bounds__(256) gemm_scores25()
{
    __shared__ float Qs[8][32];
    __shared__ float Ks[8][128];
    int g = blockIdx.y, b = g >> 3;
    int bn = blockIdx.x * 128;
    int tid = threadIdx.x;
    int lr = tid >> 1, lc = (tid & 1) * 4;
    int col = tid & 127, rg = tid >> 7;       // 0/1
    float acc[13];
    #pragma unroll
    for (int i = 0; i < 13; i++) acc[i] = 0.f;
    for (int k0 = 0; k0 < HDp; k0 += 8) {
        float4 kv = *(const float4*)(g_K + ((size_t)g*SEQ + bn + lr)*HDp + k0 + lc);
        Ks[lc+0][lr]=kv.x; Ks[lc+1][lr]=kv.y; Ks[lc+2][lr]=kv.z; Ks[lc+3][lr]=kv.w;
        if (tid < 50) {
            int qr = tid >> 1;
            float4 qv = *(const float4*)(g_Q + ((size_t)g*25 + qr)*HDp + k0 + lc);
            Qs[lc+0][qr]=qv.x; Qs[lc+1][qr]=qv.y; Qs[lc+2][qr]=qv.z; Qs[lc+3][qr]=qv.w;
        }
        __syncthreads();
        #pragma unroll
        for (int kk = 0; kk < 8; kk++) {
            float bvv = Ks[kk][col];
            #pragma unroll
            for (int i = 0; i < 13; i++) {
                int r = rg + 2*i;
                if (r < 25) acc[i] = fmaf(Qs[kk][r], bvv, acc[i]);
            }
        }
        __syncthreads();
    }
    const float scale = rsqrtf((float)HDp);
    float bias = g_bias[b*SEQ + bn + col];
    #pragma unroll
    for (int i = 0; i < 13; i++) {
        int r = rg + 2*i;
        if (r < 25)
            g_P[((size_t)g*25 + r)*SEQ + bn + col] = acc[i]*scale + bias;
    }
}

// ---------------- row softmax over g_P (row = blockIdx.x, width 512) --------
__global__ void softmax_rows()
{
    size_t row = blockIdx.x;
    float* p = g_P + row * SEQ;
    int tid = threadIdx.x;                 // 256 threads, 512 cols
    float v0 = p[tid], v1 = p[tid + 256];
    __shared__ float red[256];
    red[tid] = fmaxf(v0, v1);
    __syncthreads();
    for (int s = 128; s > 0; s >>= 1) {
        if (tid < s) red[tid] = fmaxf(red[tid], red[tid + s]);
        __syncthreads();
    }
    float m = red[0];
    __syncthreads();
    float e0 = expf(v0 - m), e1 = expf(v1 - m);
    red[tid] = e0 + e1;
    __syncthreads();
    for (int s = 128; s > 0; s >>= 1) {
        if (tid < s) red[tid] += red[tid + s];
        __syncthreads();
    }
    float inv = 1.f / red[0];
    p[tid]       = e0 * inv;
    p[tid + 256] = e1 * inv;
}

// ---------------- layer-1 O = P @ V, scatter into head slot ------------------
__global__ void __launch_bounds__(256, 2) gemm_av()
{
    __shared__ float As[2][8][128];
    __shared__ float Bs[2][8][128];
    int g = blockIdx.z, b = g >> 3, h = g & 7;
    const float* A  = g_P  + (size_t)g * SEQ * SEQ;
    const float* Bw = g_Vt + (size_t)g * HDp * SEQ;
    int tid = threadIdx.x;
    int lr = tid >> 1, lc = (tid & 1) * 4, tx = tid & 15, ty = tid >> 4;
    int bm = blockIdx.y * 128, bn = blockIdx.x * 128;
    float acc[8][8] = {};
    mm_tile_db(A, Bw, SEQ, bm + lr, bn + lr, SEQ, HDp, acc, As, Bs, lr, lc, tx, ty);
    #pragma unroll
    for (int i = 0; i < 8; i++) {
        int row = bm + ty*8 + i;
        float* crow = g_ATT + ((size_t)b*SEQ + row) * DMp + h*HDp;
        #pragma unroll
        for (int j = 0; j < 8; j++) {
            int col = bn + tx*8 + j;
            if (col < HDp) crow[col] = acc[i][j];
        }
    }
}

// ---------------- layer-2 compact O = P @ V (25 rows per head) --------------
__global__ void __launch_bounds__(160) gemm_av25()
{
    int blk = blockIdx.x;
    int g = blk / 25, r = blk % 25;
    int b = g >> 3, h = g & 7;
    __shared__ float Ps[512];
    const float* prow = g_P + ((size_t)g*25 + r)*SEQ;
    int tid = threadIdx.x;                 // 160
    for (int i = tid; i < SEQ; i += 160) Ps[i] = prow[i];
    __syncthreads();
    if (tid < HDp) {
        const float* v = g_Vt + ((size_t)g*HDp + tid)*SEQ;
        float s = 0.f;
        #pragma unroll 4
        for (int t = 0; t < SEQ; t += 4) {
            float4 vv = *(const float4*)(v + t);
            s = fmaf(Ps[t],   vv.x, s);
            s = fmaf(Ps[t+1], vv.y, s);
            s = fmaf(Ps[t+2], vv.z, s);
            s = fmaf(Ps[t+3], vv.w, s);
        }
        g_ATT[((size_t)b*25 + r)*DMp + h*HDp + tid] = s;
    }
}

// ---------------- residual add + layernorm (in place on x) -------------------
__global__ void add_ln(float* __restrict__ x, const float* __restrict__ o,
                       const float* __restrict__ w, const float* __restrict__ bb)
{
    size_t row = blockIdx.x;
    float* xr = x + row * DMp;
    const float* orow = o + row * DMp;
    int tid = threadIdx.x;                 // 256 threads, 1088 cols
    float vals[5];
    int cnt = 0;
    float s = 0.f;
    for (int i = tid; i < DMp; i += 256) { float v = xr[i] + orow[i]; vals[cnt++] = v; s += v; }
    __shared__ float red[256];
    red[tid] = s; __syncthreads();
    for (int st = 128; st > 0; st >>= 1) { if (tid < st) red[tid] += red[tid + st]; __syncthreads(); }
    float mu = red[0] * (1.f / DMp);
    __syncthreads();
    float s2 = 0.f;
    for (int k = 0; k < cnt; k++) { float d = vals[k] - mu; s2 += d * d; }
    red[tid] = s2; __syncthreads();
    for (int st = 128; st > 0; st >>= 1) { if (tid < st) red[tid] += red[tid + st]; __syncthreads(); }
    float rstd = rsqrtf(red[0] * (1.f / DMp) + 1e-5f);
    int k = 0;
    for (int i = tid; i < DMp; i += 256, k++)
        xr[i] = (vals[k] - mu) * rstd * w[i] + bb[i];
}

// ---------------- gather outputs from compact layer-2 buffer -----------------
__global__ void gather_out(float* __restrict__ out)
{
    size_t idx = (size_t)blockIdx.x * blockDim.x + threadIdx.x;
    if (idx >= (size_t)Bsz * 25 * 1024) return;
    int c = (int)(idx % 1024);
    int rem = (int)(idx / 1024);
    int t = rem % 25;
    int b = rem / 25;
    float v = g_S2[((size_t)b*25 + t) * DMp + c];
    size_t o;
    if (t == 0)      o = (size_t)b * 1024 + c;
    else if (t < 13) o = (size_t)Bsz*1024 + ((size_t)b*12 + (t-1))*1024 + c;
    else             o = (size_t)Bsz*1024 + (size_t)Bsz*12*1024
                       + ((size_t)b*12 + (t-13))*1024 + c;
    out[o] = v;
}

// ---------------- launch -----------------------------------------------------
extern "C" void kernel_launch(void* const* d_in, const int* in_sizes, int n_in,
                              void* d_out, int out_size)
{
    (void)in_sizes; (void)n_in; (void)out_size;
    const float* q    = (const float*)d_in[0];
    const float* sa   = (const float*)d_in[1];
    const float* si   = (const float*)d_in[2];
    const int*   na   = (const int*)  d_in[3];
    const int*   ni   = (const int*)  d_in[4];
    const float* ref  = (const float*)d_in[5];
    const float* Wqkv = (const float*)d_in[6];
    const float* bqkv = (const float*)d_in[7];
    const float* Wo   = (const float*)d_in[8];
    const float* bo   = (const float*)d_in[9];
    const float* ln1w = (const float*)d_in[10];
    const float* ln1b = (const float*)d_in[11];
    const float* W1   = (const float*)d_in[12];
    const float* b1   = (const float*)d_in[13];
    const float* W2   = (const float*)d_in[14];
    const float* b2   = (const float*)d_in[15];
    const float* ln2w = (const float*)d_in[16];
    const float* ln2b = (const float*)d_in[17];

    float *S, *QKV, *ATT, *FFN, *S2, *O2;
    cudaGetSymbolAddress((void**)&S,   g_S);
    cudaGetSymbolAddress((void**)&QKV, g_QKV);
    cudaGetSymbolAddress((void**)&ATT, g_ATT);
    cudaGetSymbolAddress((void**)&FFN, g_FFN);
    cudaGetSymbolAddress((void**)&S2,  g_S2);
    cudaGetSymbolAddress((void**)&O2,  g_O2);

    const int elems = MROWS * DMp;
    build_S<<<elems/256, 256>>>(q, sa, si, ref, na, ni);

    // ===================== Layer 0: full 512-token path =====================
    {
        const float* wqkv = Wqkv;
        const float* bq   = bqkv;
        gemm_nt<<<dim3((3*DMp + 127)/128, MROWS/128), 256>>>(S, wqkv, bq, QKV, MROWS, 3*DMp, DMp, 0);
        unpack_qkv<<<elems/256, 256>>>();
        gemm_scores<<<dim3(SEQ/128, SEQ/128, GHEADS), 256>>>();
        softmax_rows<<<GHEADS*SEQ, 256>>>();
        gemm_av<<<dim3((HDp + 127)/128, SEQ/128, GHEADS), 256>>>();
        gemm_nt<<<dim3((DMp + 127)/128, MROWS/128), 256>>>(ATT, Wo, bo, QKV, MROWS, DMp, DMp, 0);
        add_ln<<<MROWS, 256>>>(S, QKV, ln1w, ln1b);
        gemm_nt<<<dim3(DFFp/128, MROWS/128), 256>>>(S, W1, b1, FFN, MROWS, DFFp, DMp, 1);
        gemm_nt<<<dim3((DMp + 127)/128, MROWS/128), 256>>>(FFN, W2, b2, QKV, MROWS, DMp, DFFp, 0);
        add_ln<<<MROWS, 256>>>(S, QKV, ln2w, ln2b);
    }

    // ===================== Layer 1: pruned 25-token path =====================
    {
        const float* wqkv = Wqkv + (size_t)1 * 3 * DMp * DMp;
        const float* bq   = bqkv + (size_t)1 * 3 * DMp;
        // K,V projection over all 512 tokens (rows DM..3DM of Wqkv)
        gemm_nt<<<dim3((2*DMp + 127)/128, MROWS/128), 256>>>(S, wqkv + (size_t)DMp*DMp, bq + DMp, QKV, MROWS, 2*DMp, DMp, 0);
        unpack_kv<<<elems/256, 256>>>();
        // Compact rows 0..24 per batch
        gather_S2<<<(M2*DMp + 255)/256, 256>>>();
        // Q projection over compact rows (Qc scratch in g_FFN)
        gemm_nt<<<dim3((DMp + 127)/128, (M2 + 127)/128), 256>>>(S2, wqkv, bq, FFN, M2, DMp, DMp, 0);
        unpack_q25<<<(M2*DMp + 255)/256, 256>>>();
        // Compact attention: 25 x 512 per head
        gemm_scores25<<<dim3(SEQ/128, GHEADS), 256>>>();
        softmax_rows<<<GHEADS*25, 256>>>();
        gemm_av25<<<GHEADS*25, 160>>>();
        // Output projection + LN + FFN on compact rows
        gemm_nt<<<dim3((DMp + 127)/128, (M2 + 127)/128), 256>>>(ATT, Wo + (size_t)DMp*DMp, bo + DMp, O2, M2, DMp, DMp, 0);
        add_ln<<<M2, 256>>>(S2, O2, ln1w + DMp, ln1b + DMp);
        gemm_nt<<<dim3(DFFp/128, (M2 + 127)/128), 256>>>(S2, W1 + (size_t)DFFp*DMp, b1 + DFFp, FFN, M2, DFFp, DMp, 1);
        gemm_nt<<<dim3((DMp + 127)/128, (M2 + 127)/128), 256>>>(FFN, W2 + (size_t)DMp*DFFp, b2 + DMp, O2, M2, DMp, DFFp, 0);
        add_ln<<<M2, 256>>>(S2, O2, ln2w + DMp, ln2b + DMp);
    }

    gather_out<<<(Bsz*25*1024)/256, 256>>>((float*)d_out);
}

// round 3
// speedup vs baseline: 3.4412x; 2.1017x over previous
#include <cuda_runtime.h>
#include <math.h>
#include <stdint.h>

#define Bsz   64
#define Dd    1024
#define AEDp  64
#define DMp   1088
#define Hh    8
#define HDp   136
#define DFFp  2048
#define SEQ   512
#define Rr    487
#define MROWS (Bsz*SEQ)     /* 32768 */
#define GHEADS (Bsz*Hh)     /* 512  */
#define M2    (Bsz*25)      /* 1600 compact rows for layer 2 */

// ---------------- scratch (device globals; no runtime allocation) ----------
__device__ float g_S  [(size_t)MROWS*DMp];
__device__ float g_QKV[(size_t)MROWS*3*DMp];
__device__ float g_Q  [(size_t)GHEADS*SEQ*HDp];
__device__ float g_K  [(size_t)GHEADS*SEQ*HDp];
__device__ float g_Vt [(size_t)GHEADS*HDp*SEQ];
__device__ float g_P  [(size_t)GHEADS*SEQ*SEQ];
__device__ float g_ATT[(size_t)MROWS*DMp];
__device__ float g_FFN[(size_t)MROWS*DFFp];
__device__ float g_S2 [(size_t)M2*DMp];
__device__ float g_O2 [(size_t)M2*DMp];
__device__ float g_bias[Bsz*SEQ];

// ---------------- build S tensor + mask bias --------------------------------
__global__ void build_S(const float* __restrict__ q, const float* __restrict__ sa,
                        const float* __restrict__ si, const float* __restrict__ ref,
                        const int* __restrict__ na, const int* __restrict__ ni)
{
    size_t idx = (size_t)blockIdx.x * blockDim.x + threadIdx.x;
    if (idx >= (size_t)MROWS * DMp) return;
    int c = (int)(idx % DMp);
    size_t row = idx / DMp;
    int t = (int)(row % SEQ);
    int b = (int)(row / SEQ);
    float v;
    if (t == 0)       v = (c < Dd) ? q  [(size_t)b*Dd + c]              : 0.f;
    else if (t < 13)  v = (c < Dd) ? sa [((size_t)b*12 + (t-1))*Dd + c] : 1.f;
    else if (t < 25)  v = (c < Dd) ? si [((size_t)b*12 + (t-13))*Dd + c]: -1.f;
    else              v = (c < Dd) ? ref[((size_t)b*Rr + (t-25))*Dd + c]: 0.f;
    g_S[idx] = v;
    if (c == 0) {
        int ra = na[b], ri = ni[b];
        bool m = (t == 0)
              || (t >= 1  && t < 13 && t < ra + 1)
              || (t >= 13 && t < 25 && t < ri + 13);
        g_bias[b*SEQ + t] = m ? -1.0e9f : 0.f;
    }
}

// ================= tf32 tensor-core GEMM engine ==============================
// C = A @ B^T. A: [M,K] row-major, Bw: [N,K] row-major. K multiple of 8.
// Block 128x128, 256 threads = 8 warps (2x4), warp tile 64x32 (4x4 m16n8k8).

#define SMS 136   /* smem row stride: 8*? -> conflict-free fragment LDS */

__device__ __forceinline__ uint32_t f2tf32(float x) {
    uint32_t r; asm("cvt.rna.tf32.f32 %0, %1;" : "=r"(r) : "f"(x)); return r;
}

__device__ __forceinline__ void mma_tf32(float (&d)[4], const uint32_t (&a)[4],
                                         const uint32_t (&b)[2]) {
    asm volatile(
        "mma.sync.aligned.m16n8k8.row.col.f32.tf32.tf32.f32 "
        "{%0,%1,%2,%3}, {%4,%5,%6,%7}, {%8,%9}, {%0,%1,%2,%3};"
        : "+f"(d[0]), "+f"(d[1]), "+f"(d[2]), "+f"(d[3])
        : "r"(a[0]), "r"(a[1]), "r"(a[2]), "r"(a[3]), "r"(b[0]), "r"(b[1]));
}

__device__ __forceinline__ void tc_store4(float (*S)[SMS], int lc, int lr, float4 v) {
    S[lc+0][lr] = __uint_as_float(f2tf32(v.x));
    S[lc+1][lr] = __uint_as_float(f2tf32(v.y));
    S[lc+2][lr] = __uint_as_float(f2tf32(v.z));
    S[lc+3][lr] = __uint_as_float(f2tf32(v.w));
}

__device__ __forceinline__ void tc_compute(
    float (&acc)[4][4][4], const float (*As)[SMS], const float (*Bs)[SMS],
    int mb, int nb, int gid, int tig)
{
    uint32_t a[4][4], b[4][2];
    #pragma unroll
    for (int mi = 0; mi < 4; mi++) {
        int m = mb + mi*16 + gid;
        a[mi][0] = __float_as_uint(As[tig  ][m]);
        a[mi][1] = __float_as_uint(As[tig  ][m+8]);
        a[mi][2] = __float_as_uint(As[tig+4][m]);
        a[mi][3] = __float_as_uint(As[tig+4][m+8]);
    }
    #pragma unroll
    for (int ni = 0; ni < 4; ni++) {
        int n = nb + ni*8 + gid;
        b[ni][0] = __float_as_uint(Bs[tig  ][n]);
        b[ni][1] = __float_as_uint(Bs[tig+4][n]);
    }
    #pragma unroll
    for (int mi = 0; mi < 4; mi++)
        #pragma unroll
        for (int ni = 0; ni < 4; ni++)
            mma_tf32(acc[mi][ni], a[mi], b[ni]);
}

__device__ __forceinline__ void tc_mainloop(
    const float* __restrict__ A, const float* __restrict__ Bw, int K,
    int aRow, int bRow, bool aval, bool bval,
    float (&As)[2][8][SMS], float (&Bs)[2][8][SMS],
    float (&acc)[4][4][4],
    int lr, int lc, int mb, int nb, int gid, int tig)
{
    const float* Ap = A  + (size_t)aRow * K;
    const float* Bp = Bw + (size_t)bRow * K;
    const float4 z = make_float4(0.f,0.f,0.f,0.f);
    float4 av = aval ? *(const float4*)(Ap + lc) : z;
    float4 bv = bval ? *(const float4*)(Bp + lc) : z;
    tc_store4(As[0], lc, lr, av);
    tc_store4(Bs[0], lc, lr, bv);
    __syncthreads();
    int buf = 0;
    for (int k0 = 8; k0 < K; k0 += 8) {
        float4 av2 = aval ? *(const float4*)(Ap + k0 + lc) : z;
        float4 bv2 = bval ? *(const float4*)(Bp + k0 + lc) : z;
        tc_compute(acc, As[buf], Bs[buf], mb, nb, gid, tig);
        tc_store4(As[buf^1], lc, lr, av2);
        tc_store4(Bs[buf^1], lc, lr, bv2);
        __syncthreads();
        buf ^= 1;
    }
    tc_compute(acc, As[buf], Bs[buf], mb, nb, gid, tig);
}

// ---------------- generic tc GEMM: C = A @ W^T + bias, optional relu --------
__global__ void __launch_bounds__(256, 2)
gemm_nt_tc(const float* __restrict__ A, const float* __restrict__ Bw,
           const float* __restrict__ bias, float* __restrict__ C,
           int M, int N, int K, int relu)
{
    __shared__ float As[2][8][SMS];
    __shared__ float Bs[2][8][SMS];
    int tid = threadIdx.x, lane = tid & 31, wid = tid >> 5;
    int lr = tid >> 1, lc = (tid & 1) * 4;
    int mb = (wid >> 2) * 64, nb = (wid & 3) * 32;
    int gid = lane >> 2, tig = lane & 3;
    int bm = blockIdx.y * 128, bn = blockIdx.x * 128;
    float acc[4][4][4] = {};
    tc_mainloop(A, Bw, K, bm + lr, bn + lr, bm + lr < M, bn + lr < N,
                As, Bs, acc, lr, lc, mb, nb, gid, tig);
    #pragma unroll
    for (int mi = 0; mi < 4; mi++) {
        int row = bm + mb + mi*16 + gid;
        #pragma unroll
        for (int ni = 0; ni < 4; ni++) {
            int col = bn + nb + ni*8 + tig*2;
            if (col >= N) continue;
            float b0 = bias[col], b1 = bias[col+1];
            if (row < M) {
                float2 v = make_float2(acc[mi][ni][0] + b0, acc[mi][ni][1] + b1);
                if (relu) { v.x = fmaxf(v.x, 0.f); v.y = fmaxf(v.y, 0.f); }
                *(float2*)(C + (size_t)row * N + col) = v;
            }
            if (row + 8 < M) {
                float2 v = make_float2(acc[mi][ni][2] + b0, acc[mi][ni][3] + b1);
                if (relu) { v.x = fmaxf(v.x, 0.f); v.y = fmaxf(v.y, 0.f); }
                *(float2*)(C + (size_t)(row + 8) * N + col) = v;
            }
        }
    }
}

// ---------------- layer-1 batched scores (tc): P = scale*Q@K^T + bias -------
__global__ void __launch_bounds__(256, 2) gemm_scores_tc()
{
    __shared__ float As[2][8][SMS];
    __shared__ float Bs[2][8][SMS];
    int g = blockIdx.z, b = g >> 3;
    const float* A  = g_Q + (size_t)g * SEQ * HDp;
    const float* Bw = g_K + (size_t)g * SEQ * HDp;
    float* C = g_P + (size_t)g * SEQ * SEQ;
    int tid = threadIdx.x, lane = tid & 31, wid = tid >> 5;
    int lr = tid >> 1, lc = (tid & 1) * 4;
    int mb = (wid >> 2) * 64, nb = (wid & 3) * 32;
    int gid = lane >> 2, tig = lane & 3;
    int bm = blockIdx.y * 128, bn = blockIdx.x * 128;
    float acc[4][4][4] = {};
    tc_mainloop(A, Bw, HDp, bm + lr, bn + lr, true, true,
                As, Bs, acc, lr, lc, mb, nb, gid, tig);
    const float scale = rsqrtf((float)HDp);
    #pragma unroll
    for (int mi = 0; mi < 4; mi++) {
        int row = bm + mb + mi*16 + gid;
        #pragma unroll
        for (int ni = 0; ni < 4; ni++) {
            int col = bn + nb + ni*8 + tig*2;
            float b0 = g_bias[b*SEQ + col], b1 = g_bias[b*SEQ + col + 1];
            *(float2*)(C + (size_t)row * SEQ + col) =
                make_float2(acc[mi][ni][0]*scale + b0, acc[mi][ni][1]*scale + b1);
            *(float2*)(C + (size_t)(row+8) * SEQ + col) =
                make_float2(acc[mi][ni][2]*scale + b0, acc[mi][ni][3]*scale + b1);
        }
    }
}

// ---------------- layer-1 O = P @ V (tc), scatter into head slot ------------
__global__ void __launch_bounds__(256, 2) gemm_av_tc()
{
    __shared__ float As[2][8][SMS];
    __shared__ float Bs[2][8][SMS];
    int g = blockIdx.z, b = g >> 3, h = g & 7;
    const float* A  = g_P  + (size_t)g * SEQ * SEQ;
    const float* Bw = g_Vt + (size_t)g * HDp * SEQ;
    int tid = threadIdx.x, lane = tid & 31, wid = tid >> 5;
    int lr = tid >> 1, lc = (tid & 1) * 4;
    int mb = (wid >> 2) * 64, nb = (wid & 3) * 32;
    int gid = lane >> 2, tig = lane & 3;
    int bm = blockIdx.y * 128, bn = blockIdx.x * 128;
    float acc[4][4][4] = {};
    tc_mainloop(A, Bw, SEQ, bm + lr, bn + lr, true, bn + lr < HDp,
                As, Bs, acc, lr, lc, mb, nb, gid, tig);
    #pragma unroll
    for (int mi = 0; mi < 4; mi++) {
        int row = bm + mb + mi*16 + gid;
        #pragma unroll
        for (int ni = 0; ni < 4; ni++) {
            int col = bn + nb + ni*8 + tig*2;
            if (col >= HDp) continue;
            float* base = g_ATT + ((size_t)b*SEQ + row) * DMp + h*HDp + col;
            *(float2*)(base) = make_float2(acc[mi][ni][0], acc[mi][ni][1]);
            *(float2*)(base + (size_t)8*DMp) = make_float2(acc[mi][ni][2], acc[mi][ni][3]);
        }
    }
}

// ---------------- layer-1 unpack QKV into per-head buffers ------------------
__global__ void unpack_qkv()
{
    size_t idx = (size_t)blockIdx.x * blockDim.x + threadIdx.x;
    if (idx >= (size_t)MROWS * DMp) return;
    int c = (int)(idx % DMp);
    size_t row = idx / DMp;
    int t = (int)(row % SEQ);
    int b = (int)(row / SEQ);
    int h = c / HDp, d = c % HDp;
    const float* src = g_QKV + row * (size_t)(3*DMp);
    size_t gh = (size_t)(b*Hh + h);
    g_Q [(gh*SEQ + t)*HDp + d] = src[c];
    g_K [(gh*SEQ + t)*HDp + d] = src[DMp + c];
    g_Vt[(gh*HDp + d)*SEQ + t] = src[2*DMp + c];
}

// ---------------- layer-2 unpack KV ------------------------------------------
__global__ void unpack_kv()
{
    size_t idx = (size_t)blockIdx.x * blockDim.x + threadIdx.x;
    if (idx >= (size_t)MROWS * DMp) return;
    int c = (int)(idx % DMp);
    size_t row = idx / DMp;
    int t = (int)(row % SEQ);
    int b = (int)(row / SEQ);
    int h = c / HDp, d = c % HDp;
    const float* src = g_QKV + row * (size_t)(2*DMp);
    size_t gh = (size_t)(b*Hh + h);
    g_K [(gh*SEQ + t)*HDp + d] = src[c];
    g_Vt[(gh*HDp + d)*SEQ + t] = src[DMp + c];
}

// ---------------- gather compact layer-2 rows --------------------------------
__global__ void gather_S2()
{
    size_t idx = (size_t)blockIdx.x * blockDim.x + threadIdx.x;
    if (idx >= (size_t)M2 * DMp) return;
    int c = (int)(idx % DMp);
    int i = (int)(idx / DMp);
    int t = i % 25, b = i / 25;
    g_S2[idx] = g_S[((size_t)b*SEQ + t)*DMp + c];
}

// ---------------- layer-2 unpack compact Q (Qc lives in g_FFN) --------------
__global__ void unpack_q25()
{
    size_t idx = (size_t)blockIdx.x * blockDim.x + threadIdx.x;
    if (idx >= (size_t)M2 * DMp) return;
    int c = (int)(idx % DMp);
    int i = (int)(idx / DMp);
    int t = i % 25, b = i / 25;
    int h = c / HDp, d = c % HDp;
    int g = b*Hh + h;
    g_Q[((size_t)g*25 + t)*HDp + d] = g_FFN[(size_t)i*DMp + c];
}

// ---------------- layer-2 compact scores: 25 x 512 per head -----------------
__global__ void __launch_bounds__(256) gemm_scores25()
{
    __shared__ float Qs[8][32];
    __shared__ float Ks[8][128];
    int g = blockIdx.y, b = g >> 3;
    int bn = blockIdx.x * 128;
    int tid = threadIdx.x;
    int lr = tid >> 1, lc = (tid & 1) * 4;
    int col = tid & 127, rg = tid >> 7;
    float acc[13];
    #pragma unroll
    for (int i = 0; i < 13; i++) acc[i] = 0.f;
    for (int k0 = 0; k0 < HDp; k0 += 8) {
        float4 kv = *(const float4*)(g_K + ((size_t)g*SEQ + bn + lr)*HDp + k0 + lc);
        Ks[lc+0][lr]=kv.x; Ks[lc+1][lr]=kv.y; Ks[lc+2][lr]=kv.z; Ks[lc+3][lr]=kv.w;
        if (tid < 50) {
            int qr = tid >> 1;
            float4 qv = *(const float4*)(g_Q + ((size_t)g*25 + qr)*HDp + k0 + lc);
            Qs[lc+0][qr]=qv.x; Qs[lc+1][qr]=qv.y; Qs[lc+2][qr]=qv.z; Qs[lc+3][qr]=qv.w;
        }
        __syncthreads();
        #pragma unroll
        for (int kk = 0; kk < 8; kk++) {
            float bvv = Ks[kk][col];
            #pragma unroll
            for (int i = 0; i < 13; i++) {
                int r = rg + 2*i;
                if (r < 25) acc[i] = fmaf(Qs[kk][r], bvv, acc[i]);
            }
        }
        __syncthreads();
    }
    const float scale = rsqrtf((float)HDp);
    float bias = g_bias[b*SEQ + bn + col];
    #pragma unroll
    for (int i = 0; i < 13; i++) {
        int r = rg + 2*i;
        if (r < 25)
            g_P[((size_t)g*25 + r)*SEQ + bn + col] = acc[i]*scale + bias;
    }
}

// ---------------- row softmax over g_P ---------------------------------------
__global__ void softmax_rows()
{
    size_t row = blockIdx.x;
    float* p = g_P + row * SEQ;
    int tid = threadIdx.x;
    float v0 = p[tid], v1 = p[tid + 256];
    __shared__ float red[256];
    red[tid] = fmaxf(v0, v1);
    __syncthreads();
    for (int s = 128; s > 0; s >>= 1) {
        if (tid < s) red[tid] = fmaxf(red[tid], red[tid + s]);
        __syncthreads();
    }
    float m = red[0];
    __syncthreads();
    float e0 = expf(v0 - m), e1 = expf(v1 - m);
    red[tid] = e0 + e1;
    __syncthreads();
    for (int s = 128; s > 0; s >>= 1) {
        if (tid < s) red[tid] += red[tid + s];
        __syncthreads();
    }
    float inv = 1.f / red[0];
    p[tid]       = e0 * inv;
    p[tid + 256] = e1 * inv;
}

// ---------------- layer-2 compact O = P @ V (25 rows per head) --------------
__global__ void __launch_bounds__(160) gemm_av25()
{
    int blk = blockIdx.x;
    int g = blk / 25, r = blk % 25;
    int b = g >> 3, h = g & 7;
    __shared__ float Ps[512];
    const float* prow = g_P + ((size_t)g*25 + r)*SEQ;
    int tid = threadIdx.x;
    for (int i = tid; i < SEQ; i += 160) Ps[i] = prow[i];
    __syncthreads();
    if (tid < HDp) {
        const float* v = g_Vt + ((size_t)g*HDp + tid)*SEQ;
        float s = 0.f;
        #pragma unroll 4
        for (int t = 0; t < SEQ; t += 4) {
            float4 vv = *(const float4*)(v + t);
            s = fmaf(Ps[t],   vv.x, s);
            s = fmaf(Ps[t+1], vv.y, s);
            s = fmaf(Ps[t+2], vv.z, s);
            s = fmaf(Ps[t+3], vv.w, s);
        }
        g_ATT[((size_t)b*25 + r)*DMp + h*HDp + tid] = s;
    }
}

// ---------------- residual add + layernorm (in place on x) -------------------
__global__ void add_ln(float* __restrict__ x, const float* __restrict__ o,
                       const float* __restrict__ w, const float* __restrict__ bb)
{
    size_t row = blockIdx.x;
    float* xr = x + row * DMp;
    const float* orow = o + row * DMp;
    int tid = threadIdx.x;
    float vals[5];
    int cnt = 0;
    float s = 0.f;
    for (int i = tid; i < DMp; i += 256) { float v = xr[i] + orow[i]; vals[cnt++] = v; s += v; }
    __shared__ float red[256];
    red[tid] = s; __syncthreads();
    for (int st = 128; st > 0; st >>= 1) { if (tid < st) red[tid] += red[tid + st]; __syncthreads(); }
    float mu = red[0] * (1.f / DMp);
    __syncthreads();
    float s2 = 0.f;
    for (int k = 0; k < cnt; k++) { float d = vals[k] - mu; s2 += d * d; }
    red[tid] = s2; __syncthreads();
    for (int st = 128; st > 0; st >>= 1) { if (tid < st) red[tid] += red[tid + st]; __syncthreads(); }
    float rstd = rsqrtf(red[0] * (1.f / DMp) + 1e-5f);
    int k = 0;
    for (int i = tid; i < DMp; i += 256, k++)
        xr[i] = (vals[k] - mu) * rstd * w[i] + bb[i];
}

// ---------------- gather outputs from compact layer-2 buffer -----------------
__global__ void gather_out(float* __restrict__ out)
{
    size_t idx = (size_t)blockIdx.x * blockDim.x + threadIdx.x;
    if (idx >= (size_t)Bsz * 25 * 1024) return;
    int c = (int)(idx % 1024);
    int rem = (int)(idx / 1024);
    int t = rem % 25;
    int b = rem / 25;
    float v = g_S2[((size_t)b*25 + t) * DMp + c];
    size_t o;
    if (t == 0)      o = (size_t)b * 1024 + c;
    else if (t < 13) o = (size_t)Bsz*1024 + ((size_t)b*12 + (t-1))*1024 + c;
    else             o = (size_t)Bsz*1024 + (size_t)Bsz*12*1024
                       + ((size_t)b*12 + (t-13))*1024 + c;
    out[o] = v;
}

// ---------------- launch -----------------------------------------------------
extern "C" void kernel_launch(void* const* d_in, const int* in_sizes, int n_in,
                              void* d_out, int out_size)
{
    (void)in_sizes; (void)n_in; (void)out_size;
    const float* q    = (const float*)d_in[0];
    const float* sa   = (const float*)d_in[1];
    const float* si   = (const float*)d_in[2];
    const int*   na   = (const int*)  d_in[3];
    const int*   ni   = (const int*)  d_in[4];
    const float* ref  = (const float*)d_in[5];
    const float* Wqkv = (const float*)d_in[6];
    const float* bqkv = (const float*)d_in[7];
    const float* Wo   = (const float*)d_in[8];
    const float* bo   = (const float*)d_in[9];
    const float* ln1w = (const float*)d_in[10];
    const float* ln1b = (const float*)d_in[11];
    const float* W1   = (const float*)d_in[12];
    const float* b1   = (const float*)d_in[13];
    const float* W2   = (const float*)d_in[14];
    const float* b2   = (const float*)d_in[15];
    const float* ln2w = (const float*)d_in[16];
    const float* ln2b = (const float*)d_in[17];

    float *S, *QKV, *ATT, *FFN, *S2, *O2;
    cudaGetSymbolAddress((void**)&S,   g_S);
    cudaGetSymbolAddress((void**)&QKV, g_QKV);
    cudaGetSymbolAddress((void**)&ATT, g_ATT);
    cudaGetSymbolAddress((void**)&FFN, g_FFN);
    cudaGetSymbolAddress((void**)&S2,  g_S2);
    cudaGetSymbolAddress((void**)&O2,  g_O2);

    const int elems = MROWS * DMp;
    build_S<<<elems/256, 256>>>(q, sa, si, ref, na, ni);

    // ===================== Layer 0: full 512-token path =====================
    {
        gemm_nt_tc<<<dim3((3*DMp + 127)/128, MROWS/128), 256>>>(S, Wqkv, bqkv, QKV, MROWS, 3*DMp, DMp, 0);
        unpack_qkv<<<elems/256, 256>>>();
        gemm_scores_tc<<<dim3(SEQ/128, SEQ/128, GHEADS), 256>>>();
        softmax_rows<<<GHEADS*SEQ, 256>>>();
        gemm_av_tc<<<dim3((HDp + 127)/128, SEQ/128, GHEADS), 256>>>();
        gemm_nt_tc<<<dim3((DMp + 127)/128, MROWS/128), 256>>>(ATT, Wo, bo, QKV, MROWS, DMp, DMp, 0);
        add_ln<<<MROWS, 256>>>(S, QKV, ln1w, ln1b);
        gemm_nt_tc<<<dim3(DFFp/128, MROWS/128), 256>>>(S, W1, b1, FFN, MROWS, DFFp, DMp, 1);
        gemm_nt_tc<<<dim3((DMp + 127)/128, MROWS/128), 256>>>(FFN, W2, b2, QKV, MROWS, DMp, DFFp, 0);
        add_ln<<<MROWS, 256>>>(S, QKV, ln2w, ln2b);
    }

    // ===================== Layer 1: pruned 25-token path =====================
    {
        const float* wqkv = Wqkv + (size_t)1 * 3 * DMp * DMp;
        const float* bq   = bqkv + (size_t)1 * 3 * DMp;
        gemm_nt_tc<<<dim3((2*DMp + 127)/128, MROWS/128), 256>>>(S, wqkv + (size_t)DMp*DMp, bq + DMp, QKV, MROWS, 2*DMp, DMp, 0);
        unpack_kv<<<elems/256, 256>>>();
        gather_S2<<<(M2*DMp + 255)/256, 256>>>();
        gemm_nt_tc<<<dim3((DMp + 127)/128, (M2 + 127)/128), 256>>>(S2, wqkv, bq, FFN, M2, DMp, DMp, 0);
        unpack_q25<<<(M2*DMp + 255)/256, 256>>>();
        gemm_scores25<<<dim3(SEQ/128, GHEADS), 256>>>();
        softmax_rows<<<GHEADS*25, 256>>>();
        gemm_av25<<<GHEADS*25, 160>>>();
        gemm_nt_tc<<<dim3((DMp + 127)/128, (M2 + 127)/128), 256>>>(ATT, Wo + (size_t)DMp*DMp, bo + DMp, O2, M2, DMp, DMp, 0);
        add_ln<<<M2, 256>>>(S2, O2, ln1w + DMp, ln1b + DMp);
        gemm_nt_tc<<<dim3(DFFp/128, (M2 + 127)/128), 256>>>(S2, W1 + (size_t)DFFp*DMp, b1 + DFFp, FFN, M2, DFFp, DMp, 1);
        gemm_nt_tc<<<dim3((DMp + 127)/128, (M2 + 127)/128), 256>>>(FFN, W2 + (size_t)DMp*DFFp, b2 + DMp, O2, M2, DMp, DFFp, 0);
        add_ln<<<M2, 256>>>(S2, O2, ln2w + DMp, ln2b + DMp);
    }

    gather_out<<<(Bsz*25*1024)/256, 256>>>((float*)d_out);
}